// round 16
// baseline (speedup 1.0000x reference)
#include <cuda_runtime.h>
#include <cuda_bf16.h>
#include <math.h>
#include <stdint.h>

// ---------------- model dims ----------------
#define Bz   2
#define Ss   1024
#define Tt   (Bz*Ss)        // 2048 tokens
#define Dd   1024
#define Hh   16
#define KVh  4
#define HDd  64
#define Ll   4
#define Ee   8
#define Ff   1024
#define Vv   32000

// gemm128 dynamic smem: (hi,lo) float2 tiles, double buffered
#define A128_F2 (2*128*20)
#define B128_F2 (2*16*132)
#define SMEM128_BYTES ((A128_F2 + B128_F2) * 8)   // 74752 B

// ---------------- scratch (device globals; no allocation) ----------------
__device__ float g_x[Tt*Dd];
__device__ float g_h[Tt*Dd];
__device__ float g_q[Tt*Hh*HDd];
__device__ float g_k[Tt*KVh*HDd];
__device__ float g_v[Tt*KVh*HDd];
__device__ float g_scores[(size_t)Bz*Hh*Ss*Ss];   // 134 MB
__device__ float g_o[Tt*Hh*HDd];
__device__ float g_gbuf[(size_t)Ee*Tt*Ff];        // 67 MB per-expert gate
__device__ float g_ubuf[(size_t)Ee*Tt*Ff];        // 67 MB per-expert up
__device__ float g_dbuf[(size_t)Ee*Tt*Dd];        // 67 MB per-slot down output
__device__ int   g_eidx[Ee*Tt];
__device__ float g_egate[Ee*Tt];
__device__ int   g_ecnt[Ee];
__device__ int   g_slot[2*Tt];                    // token -> its two (e*Tt+pos) slots

// ---------------- helpers ----------------
__device__ __forceinline__ float tf32r(float x) {
    uint32_t u;
    asm("cvt.rna.tf32.f32 %0, %1;" : "=r"(u) : "f"(x));
    return __uint_as_float(u);
}

// split v into (hi, lo) tf32 pair packed in float2
__device__ __forceinline__ float2 sp2(float v) {
    float h = tf32r(v);
    return make_float2(h, tf32r(v - h));
}

__device__ __forceinline__ void mma8(float* c, const uint32_t* a, const uint32_t* b) {
    asm volatile("mma.sync.aligned.m16n8k8.row.col.f32.tf32.tf32.f32 "
                 "{%0,%1,%2,%3}, {%4,%5,%6,%7}, {%8,%9}, {%0,%1,%2,%3};"
                 : "+f"(c[0]), "+f"(c[1]), "+f"(c[2]), "+f"(c[3])
                 : "r"(a[0]), "r"(a[1]), "r"(a[2]), "r"(a[3]),
                   "r"(b[0]), "r"(b[1]));
}

__device__ __forceinline__ float blockReduceSum256(float v) {
    __shared__ float sh[32];
    int lane = threadIdx.x & 31, wid = threadIdx.x >> 5;
    #pragma unroll
    for (int o = 16; o; o >>= 1) v += __shfl_xor_sync(0xffffffffu, v, o);
    if (lane == 0) sh[wid] = v;
    __syncthreads();
    int nw = (blockDim.x + 31) >> 5;
    float r = (threadIdx.x < nw) ? sh[threadIdx.x] : 0.f;
    if (wid == 0) {
        #pragma unroll
        for (int o = 16; o; o >>= 1) r += __shfl_xor_sync(0xffffffffu, r, o);
        if (lane == 0) sh[0] = r;
    }
    __syncthreads();
    float out = sh[0];
    __syncthreads();
    return out;
}

__device__ __forceinline__ float blockReduceMax256(float v) {
    __shared__ float sh[32];
    int lane = threadIdx.x & 31, wid = threadIdx.x >> 5;
    #pragma unroll
    for (int o = 16; o; o >>= 1) v = fmaxf(v, __shfl_xor_sync(0xffffffffu, v, o));
    if (lane == 0) sh[wid] = v;
    __syncthreads();
    int nw = (blockDim.x + 31) >> 5;
    float r = (threadIdx.x < nw) ? sh[threadIdx.x] : -INFINITY;
    if (wid == 0) {
        #pragma unroll
        for (int o = 16; o; o >>= 1) r = fmaxf(r, __shfl_xor_sync(0xffffffffu, r, o));
        if (lane == 0) sh[0] = r;
    }
    __syncthreads();
    float out = sh[0];
    __syncthreads();
    return out;
}

// ---------------- elementwise kernels ----------------
__global__ void embed_k(const int* __restrict__ tok, const float* __restrict__ emb,
                        float* __restrict__ x) {
    int i = blockIdx.x * 256 + threadIdx.x;
    int t = i / Dd, d = i % Dd;
    x[i] = emb[(long)tok[t] * Dd + d];
}

__global__ void rmsnorm_k(const float* __restrict__ x, const float* __restrict__ w,
                          float* __restrict__ out) {
    int row = blockIdx.x;
    const float* xr = x + (long)row * Dd;
    float* orow = out + (long)row * Dd;
    float ss = 0.f;
    #pragma unroll
    for (int i = 0; i < 4; i++) {
        float v = xr[threadIdx.x + i * 256];
        ss += v * v;
    }
    float tot = blockReduceSum256(ss);
    float scale = rsqrtf(tot / (float)Dd + 1e-6f);
    #pragma unroll
    for (int i = 0; i < 4; i++) {
        int d = threadIdx.x + i * 256;
        orow[d] = xr[d] * scale * w[d];
    }
}

// fused per-head RMSNorm + RoPE over Q and K, in place. 64 threads = one (token, head)
__global__ void qknorm_rope2_k(float* __restrict__ q, float* __restrict__ k,
                               const float* __restrict__ qnw, const float* __restrict__ knw,
                               const int* __restrict__ pos) {
    int bid = blockIdx.x;
    float* v;
    const float* nw;
    int t;
    if (bid < Tt * Hh) {
        t = bid / Hh;
        v = q + (long)t * (Hh * HDd) + (bid % Hh) * HDd;
        nw = qnw;
    } else {
        int b2 = bid - Tt * Hh;
        t = b2 / KVh;
        v = k + (long)t * (KVh * HDd) + (b2 % KVh) * HDd;
        nw = knw;
    }
    int d = threadIdx.x;
    float x = v[d];
    float ss = x * x;
    #pragma unroll
    for (int o = 16; o; o >>= 1) ss += __shfl_xor_sync(0xffffffffu, ss, o);
    __shared__ float s2[2];
    if ((d & 31) == 0) s2[d >> 5] = ss;
    __syncthreads();
    float tot = s2[0] + s2[1];
    float scale = rsqrtf(tot / 64.f + 1e-6f);
    float xn = x * scale * nw[d];
    __shared__ float sh[64];
    sh[d] = xn;
    __syncthreads();
    int p = pos[t];
    int fi = d & 31;
    float inv = powf(1e6f, -(float)fi / 32.f);
    float ang = (float)p * inv;
    float c = cosf(ang), s = sinf(ang);
    float other = (d < 32) ? sh[d + 32] : sh[d - 32];
    float rot = (d < 32) ? -other : other;
    v[d] = xn * c + rot * s;
}

// causal softmax; zero-fills only (q, bandEnd) — P.V's trapezoid-K never reads past it
__global__ void softmax_k(float* __restrict__ scores) {
    long row = blockIdx.x;                 // B*H*S rows
    int q = (int)(row % Ss);
    float* p = scores + row * Ss;
    int valid = q + 1;
    float mx = -INFINITY;
    for (int j = threadIdx.x; j < valid; j += 256) mx = fmaxf(mx, p[j]);
    mx = blockReduceMax256(mx);
    float sum = 0.f;
    for (int j = threadIdx.x; j < valid; j += 256) {
        float e = expf(p[j] - mx);
        p[j] = e;
        sum += e;
    }
    sum = blockReduceSum256(sum);
    float inv = 1.f / sum;
    for (int j = threadIdx.x; j < valid; j += 256) p[j] *= inv;
    int bandEnd = ((q >> 6) + 1) << 6;
    for (int j = valid + threadIdx.x; j < bandEnd; j += 256) p[j] = 0.f;
}

__global__ void zero_cnt_k(int* c) { if (threadIdx.x < Ee) c[threadIdx.x] = 0; }

// router: logits = h @ rw [D,E]; top-2; normalize; fill expert lists + token slots
__global__ void router_k(const float* __restrict__ h, const float* __restrict__ rw,
                         int* __restrict__ ecnt, int* __restrict__ eidx,
                         float* __restrict__ egate, int* __restrict__ slot) {
    int t = blockIdx.x;
    int lane = threadIdx.x & 31, w = threadIdx.x >> 5;   // warp per expert
    const float* hr = h + (long)t * Dd;
    float s = 0.f;
    for (int d = lane; d < Dd; d += 32) s += hr[d] * rw[(long)d * Ee + w];
    #pragma unroll
    for (int o = 16; o; o >>= 1) s += __shfl_xor_sync(0xffffffffu, s, o);
    __shared__ float lg[Ee];
    if (lane == 0) lg[w] = s;
    __syncthreads();
    if (threadIdx.x == 0) {
        int a = 0;
        #pragma unroll
        for (int i = 1; i < Ee; i++) if (lg[i] > lg[a]) a = i;
        int b = (a == 0) ? 1 : 0;
        #pragma unroll
        for (int i = 0; i < Ee; i++) if (i != a && lg[i] > lg[b]) b = i;
        float wa = 1.f / (1.f + expf(lg[b] - lg[a]));
        float wb = 1.f - wa;
        int pa = atomicAdd(&ecnt[a], 1);
        eidx[a * Tt + pa] = t; egate[a * Tt + pa] = wa;
        int pb = atomicAdd(&ecnt[b], 1);
        eidx[b * Tt + pb] = t; egate[b * Tt + pb] = wb;
        slot[2 * t + 0] = a * Tt + pa;
        slot[2 * t + 1] = b * Tt + pb;
    }
}

// compacted silu*up: exactly 2*Tt active rows across experts (sum(cnt) == 2*Tt)
__global__ void silu_compact_k(float* __restrict__ g, const float* __restrict__ u,
                               const int* __restrict__ cnt) {
    long i = (long)blockIdx.x * 256 + threadIdx.x;   // [0, 2*Tt*Ff)
    int r = (int)(i / Ff), col = (int)(i % Ff);
    int e = -1, lr = 0, acc = 0;
    #pragma unroll
    for (int j = 0; j < Ee; j++) {
        int c = cnt[j];
        if (e < 0 && r < acc + c) { e = j; lr = r - acc; }
        acc += c;
    }
    if (e < 0) return;
    long idx = (long)e * ((long)Tt * Ff) + (long)lr * Ff + col;
    float x = g[idx];
    g[idx] = (x / (1.f + expf(-x))) * u[idx];
}

// deterministic combine: x[t] += gate0*dbuf[slot0] + gate1*dbuf[slot1]
__global__ void combine_k(float* __restrict__ x, const float* __restrict__ dbuf,
                          const int* __restrict__ slot, const float* __restrict__ eg) {
    long i = (long)blockIdx.x * 256 + threadIdx.x;   // Tt*Dd
    int t = (int)(i / Dd), d = (int)(i % Dd);
    int s0 = slot[2 * t], s1 = slot[2 * t + 1];
    x[i] += eg[s0] * dbuf[(long)s0 * Dd + d] + eg[s1] * dbuf[(long)s1 * Dd + d];
}

// ========== MODE semantics (both GEMM kernels) ==========
// MODE 0: batched heads via z. MODE 1: dual output. MODE 2: expert dual+gather.
// MODE 3: expert single. MODE 4 (gemm64): triple Q/K/V. kTrap: P.V trapezoid.
// smem holds (hi,lo) tf32 pairs as float2 — split once at STS, 64-bit fragment
// LDS, zero split-ALU in the MMA loop. Bank-conflict-free (see R14 analysis).
// gemm64: static smem 37.9 KB. gemm128: DYNAMIC smem 74.8 KB (static limit 48).

// ---------------- 3xTF32 GEMM, 64x64 tile (small/batched shapes) ----------------
template<int MODE, bool TRANSB>
__global__ void __launch_bounds__(128) gemm64_k(
    const float* __restrict__ A, const float* __restrict__ B,
    const float* __restrict__ B2, float* __restrict__ C, float* __restrict__ C2,
    int M, int N, int K, int lda, int ldb, int ldc,
    float alpha, int addC, int causal,
    const int* __restrict__ idxBase, const int* __restrict__ MdevBase,
    long sAb, long sAh, long sBb, long sBh, long sCb, long sCh,
    int nH, int hDiv, long eA, long eB, long eC,
    const float* __restrict__ B3, float* __restrict__ C3, int kTrap)
{
    const int* idx = nullptr;
    if (MODE == 0) {
        int z = blockIdx.z;
        int b = z / nH, h = z % nH;
        A += (long)b * sAb + (long)h * sAh;
        B += (long)b * sBb + (long)(h / hDiv) * sBh;
        C += (long)b * sCb + (long)h * sCh;
    } else if (MODE == 1) {
        if (blockIdx.z) { B = B2; C = C2; }
    } else if (MODE == 2) {
        int e = blockIdx.z >> 1, which = blockIdx.z & 1;
        M = MdevBase[e];
        idx = idxBase + e * Tt;
        B = (which ? B2 : B) + (long)e * eB;
        C = (which ? C2 : C) + (long)e * eC;
    } else if (MODE == 3) {
        int e = blockIdx.z;
        M = MdevBase[e];
        A += (long)e * eA;
        B += (long)e * eB;
        C += (long)e * eC;
    } else if (MODE == 4) {
        int z = blockIdx.z;
        if (z == 1) { B = B2; C = C2; N = KVh * HDd; ldb = KVh * HDd; ldc = KVh * HDd; }
        else if (z == 2) { B = B3; C = C3; N = KVh * HDd; ldb = KVh * HDd; ldc = KVh * HDd; }
    }
    constexpr bool GATHER = (MODE == 2);

    int m0 = blockIdx.y * 64, n0 = blockIdx.x * 64;
    if (m0 >= M || n0 >= N) return;
    if (causal && n0 >= m0 + 64) return;

    __shared__ float2 As[2][64][20];   // (hi,lo); conflict-free
    __shared__ float2 Bs[2][16][68];   // stride 68 == 4 mod 16: conflict-free

    int tid = threadIdx.x;
    int lane = tid & 31, warp = tid >> 5;
    int wm = (warp >> 1) * 32, wn = (warp & 1) * 32;
    int qrow = lane >> 2, qk = lane & 3;

    int ar_r = tid >> 2;               // 0..31
    int ac4 = (tid & 3) * 4;
    int gr0 = m0 + ar_r, gr1 = gr0 + 32;
    bool av0 = gr0 < M, av1 = gr1 < M;
    long arow0 = 0, arow1 = 0;
    if (av0) arow0 = (long)(GATHER ? idx[gr0] : gr0) * lda;
    if (av1) arow1 = (long)(GATHER ? idx[gr1] : gr1) * lda;

    int bnr, bc4;
    if (TRANSB) { bnr = tid >> 2; bc4 = (tid & 3) * 4; }
    else        { bnr = tid >> 4; bc4 = (tid & 15) * 4; }

    float4 pa0, pa1, pb0, pb1;
    const float4 z4 = make_float4(0.f, 0.f, 0.f, 0.f);

    float acc[2][4][4];
    #pragma unroll
    for (int mt = 0; mt < 2; mt++)
        #pragma unroll
        for (int nt = 0; nt < 4; nt++)
            #pragma unroll
            for (int i = 0; i < 4; i++) acc[mt][nt][i] = 0.f;

    auto LDG = [&](int k0) {
        pa0 = av0 ? *(const float4*)(A + arow0 + k0 + ac4) : z4;
        pa1 = av1 ? *(const float4*)(A + arow1 + k0 + ac4) : z4;
        if (TRANSB) {
            pb0 = *(const float4*)(B + (long)(n0 + bnr) * ldb + k0 + bc4);
            pb1 = *(const float4*)(B + (long)(n0 + bnr + 32) * ldb + k0 + bc4);
        } else {
            pb0 = *(const float4*)(B + (long)(k0 + bnr) * ldb + n0 + bc4);
            pb1 = *(const float4*)(B + (long)(k0 + bnr + 8) * ldb + n0 + bc4);
        }
    };

    auto STS = [&](int buf) {
        As[buf][ar_r][ac4 + 0] = sp2(pa0.x);
        As[buf][ar_r][ac4 + 1] = sp2(pa0.y);
        As[buf][ar_r][ac4 + 2] = sp2(pa0.z);
        As[buf][ar_r][ac4 + 3] = sp2(pa0.w);
        As[buf][ar_r + 32][ac4 + 0] = sp2(pa1.x);
        As[buf][ar_r + 32][ac4 + 1] = sp2(pa1.y);
        As[buf][ar_r + 32][ac4 + 2] = sp2(pa1.z);
        As[buf][ar_r + 32][ac4 + 3] = sp2(pa1.w);
        if (TRANSB) {
            Bs[buf][bc4 + 0][bnr] = sp2(pb0.x);
            Bs[buf][bc4 + 1][bnr] = sp2(pb0.y);
            Bs[buf][bc4 + 2][bnr] = sp2(pb0.z);
            Bs[buf][bc4 + 3][bnr] = sp2(pb0.w);
            Bs[buf][bc4 + 0][bnr + 32] = sp2(pb1.x);
            Bs[buf][bc4 + 1][bnr + 32] = sp2(pb1.y);
            Bs[buf][bc4 + 2][bnr + 32] = sp2(pb1.z);
            Bs[buf][bc4 + 3][bnr + 32] = sp2(pb1.w);
        } else {
            Bs[buf][bnr][bc4 + 0] = sp2(pb0.x);
            Bs[buf][bnr][bc4 + 1] = sp2(pb0.y);
            Bs[buf][bnr][bc4 + 2] = sp2(pb0.z);
            Bs[buf][bnr][bc4 + 3] = sp2(pb0.w);
            Bs[buf][bnr + 8][bc4 + 0] = sp2(pb1.x);
            Bs[buf][bnr + 8][bc4 + 1] = sp2(pb1.y);
            Bs[buf][bnr + 8][bc4 + 2] = sp2(pb1.z);
            Bs[buf][bnr + 8][bc4 + 3] = sp2(pb1.w);
        }
    };

    auto COMPUTE = [&](int buf) {
        #pragma unroll
        for (int ks = 0; ks < 2; ks++) {
            int kk = ks * 8 + qk;
            uint32_t afh[2][4], afl[2][4];
            #pragma unroll
            for (int mt = 0; mt < 2; mt++) {
                int r = wm + mt * 16 + qrow;
                float2 t0 = As[buf][r][kk];
                float2 t1 = As[buf][r + 8][kk];
                float2 t2 = As[buf][r][kk + 4];
                float2 t3 = As[buf][r + 8][kk + 4];
                afh[mt][0] = __float_as_uint(t0.x); afl[mt][0] = __float_as_uint(t0.y);
                afh[mt][1] = __float_as_uint(t1.x); afl[mt][1] = __float_as_uint(t1.y);
                afh[mt][2] = __float_as_uint(t2.x); afl[mt][2] = __float_as_uint(t2.y);
                afh[mt][3] = __float_as_uint(t3.x); afl[mt][3] = __float_as_uint(t3.y);
            }
            uint32_t bfh[4][2], bfl[4][2];
            #pragma unroll
            for (int nt = 0; nt < 4; nt++) {
                int cn = wn + nt * 8 + qrow;
                float2 t0 = Bs[buf][kk][cn];
                float2 t1 = Bs[buf][kk + 4][cn];
                bfh[nt][0] = __float_as_uint(t0.x); bfl[nt][0] = __float_as_uint(t0.y);
                bfh[nt][1] = __float_as_uint(t1.x); bfl[nt][1] = __float_as_uint(t1.y);
            }
            #pragma unroll
            for (int mt = 0; mt < 2; mt++)
                #pragma unroll
                for (int nt = 0; nt < 4; nt++) {
                    mma8(acc[mt][nt], afh[mt], bfl[nt]);
                    mma8(acc[mt][nt], afl[mt], bfh[nt]);
                    mma8(acc[mt][nt], afh[mt], bfh[nt]);
                }
        }
    };

    int KT = K >> 4;
    if (kTrap) {
        int kt2 = (m0 + 64) >> 4;
        if (kt2 < KT) KT = kt2;
    }
    LDG(0);
    STS(0);
    __syncthreads();
    for (int kt = 0; kt < KT; kt++) {
        int cur = kt & 1;
        bool more = (kt + 1) < KT;
        if (more) LDG((kt + 1) * 16);
        COMPUTE(cur);
        if (more) {
            __syncthreads();
            STS(cur ^ 1);
            __syncthreads();
        }
    }

    #pragma unroll
    for (int mt = 0; mt < 2; mt++) {
        #pragma unroll
        for (int half = 0; half < 2; half++) {
            int m = m0 + wm + mt * 16 + qrow + half * 8;
            if (m >= M) continue;
            long crow = (long)m * ldc;
            #pragma unroll
            for (int nt = 0; nt < 4; nt++) {
                int col = n0 + wn + nt * 8 + 2 * qk;
                float v0 = alpha * acc[mt][nt][half * 2 + 0];
                float v1 = alpha * acc[mt][nt][half * 2 + 1];
                float2* cp = (float2*)(C + crow + col);
                if (addC) {
                    float2 old = *cp;
                    old.x += v0; old.y += v1;
                    *cp = old;
                } else {
                    *cp = make_float2(v0, v1);
                }
            }
        }
    }
}

// ---------------- 3xTF32 GEMM, 128x128 tile (large shapes) ----------------
// Dynamic smem: As = dyn[0 .. A128_F2), Bs = dyn[A128_F2 ..)
template<int MODE, bool TRANSB>
__global__ void __launch_bounds__(256, 2) gemm128_k(
    const float* __restrict__ A, const float* __restrict__ B,
    const float* __restrict__ B2, float* __restrict__ C, float* __restrict__ C2,
    int M, int N, int K, int lda, int ldb, int ldc,
    float alpha, int addC, int causal,
    const int* __restrict__ idxBase, const int* __restrict__ MdevBase,
    long sAb, long sAh, long sBb, long sBh, long sCb, long sCh,
    int nH, int hDiv, long eA, long eB, long eC)
{
    const int* idx = nullptr;
    if (MODE == 0) {
        int z = blockIdx.z;
        int b = z / nH, h = z % nH;
        A += (long)b * sAb + (long)h * sAh;
        B += (long)b * sBb + (long)(h / hDiv) * sBh;
        C += (long)b * sCb + (long)h * sCh;
    } else if (MODE == 1) {
        if (blockIdx.z) { B = B2; C = C2; }
    } else if (MODE == 2) {
        int e = blockIdx.z >> 1, which = blockIdx.z & 1;
        M = MdevBase[e];
        idx = idxBase + e * Tt;
        B = (which ? B2 : B) + (long)e * eB;
        C = (which ? C2 : C) + (long)e * eC;
    } else if (MODE == 3) {
        int e = blockIdx.z;
        M = MdevBase[e];
        A += (long)e * eA;
        B += (long)e * eB;
        C += (long)e * eC;
    }
    constexpr bool GATHER = (MODE == 2);

    int m0 = blockIdx.y * 128, n0 = blockIdx.x * 128;
    if (m0 >= M) return;
    if (causal && n0 >= m0 + 128) return;

    extern __shared__ float2 dyn[];
    float2 (*As)[128][20] = (float2(*)[128][20])dyn;            // [2][128][20]
    float2 (*Bs)[16][132] = (float2(*)[16][132])(dyn + A128_F2); // [2][16][132]

    int tid = threadIdx.x;
    int lane = tid & 31, warp = tid >> 5;
    int wm = (warp >> 2) * 64, wn = (warp & 3) * 32;
    int qrow = lane >> 2, qk = lane & 3;

    int ar_r = tid >> 2;               // 0..63
    int ac4 = (tid & 3) * 4;
    int gr0 = m0 + ar_r, gr1 = gr0 + 64;
    bool av0 = gr0 < M, av1 = gr1 < M;
    long arow0 = 0, arow1 = 0;
    if (av0) arow0 = (long)(GATHER ? idx[gr0] : gr0) * lda;
    if (av1) arow1 = (long)(GATHER ? idx[gr1] : gr1) * lda;

    int bnr, bc4;
    bool bv0, bv1;
    if (TRANSB) {
        bnr = tid >> 2; bc4 = (tid & 3) * 4;       // n-rows bnr, bnr+64
        bv0 = (n0 + bnr) < N; bv1 = (n0 + bnr + 64) < N;
    } else {
        bnr = tid >> 5; bc4 = (tid & 31) * 4;      // k-rows bnr, bnr+8
        bv0 = bv1 = (n0 + bc4) < N;
    }

    float4 pa0, pa1, pb0, pb1;
    const float4 z4 = make_float4(0.f, 0.f, 0.f, 0.f);

    float acc[4][4][4];
    #pragma unroll
    for (int mt = 0; mt < 4; mt++)
        #pragma unroll
        for (int nt = 0; nt < 4; nt++)
            #pragma unroll
            for (int i = 0; i < 4; i++) acc[mt][nt][i] = 0.f;

    auto LDG = [&](int k0) {
        pa0 = av0 ? *(const float4*)(A + arow0 + k0 + ac4) : z4;
        pa1 = av1 ? *(const float4*)(A + arow1 + k0 + ac4) : z4;
        if (TRANSB) {
            pb0 = bv0 ? *(const float4*)(B + (long)(n0 + bnr) * ldb + k0 + bc4) : z4;
            pb1 = bv1 ? *(const float4*)(B + (long)(n0 + bnr + 64) * ldb + k0 + bc4) : z4;
        } else {
            pb0 = bv0 ? *(const float4*)(B + (long)(k0 + bnr) * ldb + n0 + bc4) : z4;
            pb1 = bv1 ? *(const float4*)(B + (long)(k0 + bnr + 8) * ldb + n0 + bc4) : z4;
        }
    };

    auto STS = [&](int buf) {
        As[buf][ar_r][ac4 + 0] = sp2(pa0.x);
        As[buf][ar_r][ac4 + 1] = sp2(pa0.y);
        As[buf][ar_r][ac4 + 2] = sp2(pa0.z);
        As[buf][ar_r][ac4 + 3] = sp2(pa0.w);
        As[buf][ar_r + 64][ac4 + 0] = sp2(pa1.x);
        As[buf][ar_r + 64][ac4 + 1] = sp2(pa1.y);
        As[buf][ar_r + 64][ac4 + 2] = sp2(pa1.z);
        As[buf][ar_r + 64][ac4 + 3] = sp2(pa1.w);
        if (TRANSB) {
            Bs[buf][bc4 + 0][bnr] = sp2(pb0.x);
            Bs[buf][bc4 + 1][bnr] = sp2(pb0.y);
            Bs[buf][bc4 + 2][bnr] = sp2(pb0.z);
            Bs[buf][bc4 + 3][bnr] = sp2(pb0.w);
            Bs[buf][bc4 + 0][bnr + 64] = sp2(pb1.x);
            Bs[buf][bc4 + 1][bnr + 64] = sp2(pb1.y);
            Bs[buf][bc4 + 2][bnr + 64] = sp2(pb1.z);
            Bs[buf][bc4 + 3][bnr + 64] = sp2(pb1.w);
        } else {
            Bs[buf][bnr][bc4 + 0] = sp2(pb0.x);
            Bs[buf][bnr][bc4 + 1] = sp2(pb0.y);
            Bs[buf][bnr][bc4 + 2] = sp2(pb0.z);
            Bs[buf][bnr][bc4 + 3] = sp2(pb0.w);
            Bs[buf][bnr + 8][bc4 + 0] = sp2(pb1.x);
            Bs[buf][bnr + 8][bc4 + 1] = sp2(pb1.y);
            Bs[buf][bnr + 8][bc4 + 2] = sp2(pb1.z);
            Bs[buf][bnr + 8][bc4 + 3] = sp2(pb1.w);
        }
    };

    auto COMPUTE = [&](int buf) {
        #pragma unroll
        for (int ks = 0; ks < 2; ks++) {
            int kk = ks * 8 + qk;
            uint32_t afh[4][4], afl[4][4];
            #pragma unroll
            for (int mt = 0; mt < 4; mt++) {
                int r = wm + mt * 16 + qrow;
                float2 t0 = As[buf][r][kk];
                float2 t1 = As[buf][r + 8][kk];
                float2 t2 = As[buf][r][kk + 4];
                float2 t3 = As[buf][r + 8][kk + 4];
                afh[mt][0] = __float_as_uint(t0.x); afl[mt][0] = __float_as_uint(t0.y);
                afh[mt][1] = __float_as_uint(t1.x); afl[mt][1] = __float_as_uint(t1.y);
                afh[mt][2] = __float_as_uint(t2.x); afl[mt][2] = __float_as_uint(t2.y);
                afh[mt][3] = __float_as_uint(t3.x); afl[mt][3] = __float_as_uint(t3.y);
            }
            uint32_t bfh[4][2], bfl[4][2];
            #pragma unroll
            for (int nt = 0; nt < 4; nt++) {
                int cn = wn + nt * 8 + qrow;
                float2 t0 = Bs[buf][kk][cn];
                float2 t1 = Bs[buf][kk + 4][cn];
                bfh[nt][0] = __float_as_uint(t0.x); bfl[nt][0] = __float_as_uint(t0.y);
                bfh[nt][1] = __float_as_uint(t1.x); bfl[nt][1] = __float_as_uint(t1.y);
            }
            #pragma unroll
            for (int mt = 0; mt < 4; mt++)
                #pragma unroll
                for (int nt = 0; nt < 4; nt++) {
                    mma8(acc[mt][nt], afh[mt], bfl[nt]);
                    mma8(acc[mt][nt], afl[mt], bfh[nt]);
                    mma8(acc[mt][nt], afh[mt], bfh[nt]);
                }
        }
    };

    int KT = K >> 4;
    LDG(0);
    STS(0);
    __syncthreads();
    for (int kt = 0; kt < KT; kt++) {
        int cur = kt & 1;
        bool more = (kt + 1) < KT;
        if (more) LDG((kt + 1) * 16);
        COMPUTE(cur);
        if (more) {
            __syncthreads();
            STS(cur ^ 1);
            __syncthreads();
        }
    }

    #pragma unroll
    for (int mt = 0; mt < 4; mt++) {
        #pragma unroll
        for (int half = 0; half < 2; half++) {
            int m = m0 + wm + mt * 16 + qrow + half * 8;
            if (m >= M) continue;
            long crow = (long)m * ldc;
            #pragma unroll
            for (int nt = 0; nt < 4; nt++) {
                int colg = n0 + wn + nt * 8;
                if (colg >= N) continue;
                int col = colg + 2 * qk;
                float v0 = alpha * acc[mt][nt][half * 2 + 0];
                float v1 = alpha * acc[mt][nt][half * 2 + 1];
                float2* cp = (float2*)(C + crow + col);
                if (addC) {
                    float2 old = *cp;
                    old.x += v0; old.y += v1;
                    *cp = old;
                } else {
                    *cp = make_float2(v0, v1);
                }
            }
        }
    }
}

// ---------------- host side ----------------
extern "C" void kernel_launch(void* const* d_in, const int* in_sizes, int n_in,
                              void* d_out, int out_size) {
    const int*   tok    = (const int*)d_in[0];
    const int*   pos    = (const int*)d_in[1];
    const float* emb    = (const float*)d_in[2];
    const float* attnw  = (const float*)d_in[3];
    const float* wq     = (const float*)d_in[4];
    const float* wk     = (const float*)d_in[5];
    const float* wv     = (const float*)d_in[6];
    const float* qnw    = (const float*)d_in[7];
    const float* knw    = (const float*)d_in[8];
    const float* wo     = (const float*)d_in[9];
    const float* ffnw   = (const float*)d_in[10];
    const float* rw     = (const float*)d_in[11];
    const float* gw     = (const float*)d_in[12];
    const float* uw     = (const float*)d_in[13];
    const float* dw     = (const float*)d_in[14];
    const float* fnw    = (const float*)d_in[15];
    float* out = (float*)d_out;

    // opt-in to >48KB dynamic smem for the gemm128 instantiations (idempotent)
    cudaFuncSetAttribute(gemm128_k<0,true>,
                         cudaFuncAttributeMaxDynamicSharedMemorySize, SMEM128_BYTES);
    cudaFuncSetAttribute(gemm128_k<2,false>,
                         cudaFuncAttributeMaxDynamicSharedMemorySize, SMEM128_BYTES);
    cudaFuncSetAttribute(gemm128_k<3,false>,
                         cudaFuncAttributeMaxDynamicSharedMemorySize, SMEM128_BYTES);

    float *px, *ph, *pq, *pk, *pv, *po, *pscores, *pgbuf, *pubuf, *pdbuf, *pegate;
    int *peidx, *pecnt, *pslot;
    cudaGetSymbolAddress((void**)&px, g_x);
    cudaGetSymbolAddress((void**)&ph, g_h);
    cudaGetSymbolAddress((void**)&pq, g_q);
    cudaGetSymbolAddress((void**)&pk, g_k);
    cudaGetSymbolAddress((void**)&pv, g_v);
    cudaGetSymbolAddress((void**)&po, g_o);
    cudaGetSymbolAddress((void**)&pscores, g_scores);
    cudaGetSymbolAddress((void**)&pgbuf, g_gbuf);
    cudaGetSymbolAddress((void**)&pubuf, g_ubuf);
    cudaGetSymbolAddress((void**)&pdbuf, g_dbuf);
    cudaGetSymbolAddress((void**)&pegate, g_egate);
    cudaGetSymbolAddress((void**)&peidx, g_eidx);
    cudaGetSymbolAddress((void**)&pecnt, g_ecnt);
    cudaGetSymbolAddress((void**)&pslot, g_slot);

    const long ZL = 0;

    // embed
    embed_k<<<(Tt * Dd) / 256, 256>>>(tok, emb, px);

    for (int l = 0; l < Ll; l++) {
        const float* wq_l = wq + (long)l * Dd * (Hh * HDd);
        const float* wk_l = wk + (long)l * Dd * (KVh * HDd);
        const float* wv_l = wv + (long)l * Dd * (KVh * HDd);
        const float* wo_l = wo + (long)l * (Hh * HDd) * Dd;
        const float* gw_l = gw + (long)l * Ee * Dd * Ff;
        const float* uw_l = uw + (long)l * Ee * Dd * Ff;
        const float* dw_l = dw + (long)l * Ee * Ff * Dd;

        // ---- attention ----
        rmsnorm_k<<<Tt, 256>>>(px, attnw + (long)l * Dd, ph);

        // Q + K + V fused in ONE launch (MODE 4: z=0 Q, z=1 K, z=2 V)
        gemm64_k<4,false><<<dim3(16, 32, 3), 128>>>(
            ph, wq_l, wk_l, pq, pk,
            Tt, Hh * HDd, Dd, Dd, Hh * HDd, Hh * HDd,
            1.f, 0, 0, nullptr, nullptr,
            ZL, ZL, ZL, ZL, ZL, ZL, 1, 1, ZL, ZL, ZL,
            wv_l, pv, 0);

        // fused q+k norm/rope
        qknorm_rope2_k<<<Tt * (Hh + KVh), 64>>>(pq, pk, qnw + (long)l * HDd,
                                                knw + (long)l * HDd, pos);

        // scores = Q @ K^T * scale (128-tile, batched, causal skip)
        gemm128_k<0,true><<<dim3(8, 8, Bz * Hh), 256, SMEM128_BYTES>>>(
            pq, pk, nullptr, pscores, nullptr,
            Ss, Ss, HDd, Hh * HDd, KVh * HDd, Ss,
            0.125f, 0, 1, nullptr, nullptr,
            (long)Ss * Hh * HDd, (long)HDd,
            (long)Ss * KVh * HDd, (long)HDd,
            (long)Hh * Ss * Ss, (long)Ss * Ss,
            Hh, Hh / KVh, ZL, ZL, ZL);

        softmax_k<<<Bz * Hh * Ss, 256>>>(pscores);

        // O = P @ V (64-tile, trapezoid-K: K loop bounded at m0+64)
        gemm64_k<0,false><<<dim3(1, 16, Bz * Hh), 128>>>(
            pscores, pv, nullptr, po, nullptr,
            Ss, HDd, Ss, Ss, KVh * HDd, Hh * HDd,
            1.f, 0, 0, nullptr, nullptr,
            (long)Hh * Ss * Ss, (long)Ss * Ss,
            (long)Ss * KVh * HDd, (long)HDd,
            (long)Ss * Hh * HDd, (long)HDd,
            Hh, Hh / KVh, ZL, ZL, ZL,
            nullptr, nullptr, 1);

        // x += O @ wo (64-tile: grid 512)
        gemm64_k<0,false><<<dim3(16, 32, 1), 128>>>(
            po, wo_l, nullptr, px, nullptr,
            Tt, Dd, Hh * HDd, Hh * HDd, Dd, Dd,
            1.f, 1, 0, nullptr, nullptr,
            ZL, ZL, ZL, ZL, ZL, ZL, 1, 1, ZL, ZL, ZL,
            nullptr, nullptr, 0);

        // ---- MoE ----
        rmsnorm_k<<<Tt, 256>>>(px, ffnw + (long)l * Dd, ph);
        zero_cnt_k<<<1, 32>>>(pecnt);
        router_k<<<Tt, 256>>>(ph, rw + (long)l * Dd * Ee, pecnt, peidx, pegate, pslot);

        // all experts' gate+up in ONE launch (128-tile): z = e*2 + which
        gemm128_k<2,false><<<dim3(8, 16, 2 * Ee), 256, SMEM128_BYTES>>>(
            ph, gw_l, uw_l, pgbuf, pubuf,
            Tt, Ff, Dd, Dd, Ff, Ff,
            1.f, 0, 0, peidx, pecnt,
            ZL, ZL, ZL, ZL, ZL, ZL, 1, 1,
            ZL, (long)Dd * Ff, (long)Tt * Ff);

        // compacted silu*up over exactly the 2*Tt active rows
        silu_compact_k<<<(int)(((long)2 * Tt * Ff) / 256), 256>>>(pgbuf, pubuf, pecnt);

        // all experts' down-proj in ONE launch (128-tile) -> per-slot buffer
        gemm128_k<3,false><<<dim3(8, 16, Ee), 256, SMEM128_BYTES>>>(
            pgbuf, dw_l, nullptr, pdbuf, nullptr,
            Tt, Dd, Ff, Ff, Dd, Dd,
            1.f, 0, 0, nullptr, pecnt,
            ZL, ZL, ZL, ZL, ZL, ZL, 1, 1,
            (long)Tt * Ff, (long)Ff * Dd, (long)Tt * Dd);

        // deterministic combine: x += gate0*y0 + gate1*y1
        combine_k<<<(Tt * Dd) / 256, 256>>>(px, pdbuf, pslot, pegate);
    }

    // final norm + tied lm_head (128-tile: grid 250x16 = 4000)
    rmsnorm_k<<<Tt, 256>>>(px, fnw, ph);
    gemm128_k<0,true><<<dim3(Vv / 128, Tt / 128, 1), 256, SMEM128_BYTES>>>(
        ph, emb, nullptr, out, nullptr,
        Tt, Vv, Dd, Dd, Dd, Vv,
        1.f, 0, 0, nullptr, nullptr,
        ZL, ZL, ZL, ZL, ZL, ZL, 1, 1, ZL, ZL, ZL);
}

// round 17
// speedup vs baseline: 1.1052x; 1.1052x over previous
#include <cuda_runtime.h>
#include <cuda_bf16.h>
#include <math.h>
#include <stdint.h>

// ---------------- model dims ----------------
#define Bz   2
#define Ss   1024
#define Tt   (Bz*Ss)        // 2048 tokens
#define Dd   1024
#define Hh   16
#define KVh  4
#define HDd  64
#define Ll   4
#define Ee   8
#define Ff   1024
#define Vv   32000

// ---------------- scratch (device globals; no allocation) ----------------
__device__ float g_x[Tt*Dd];
__device__ float g_h[Tt*Dd];
__device__ float g_q[Tt*Hh*HDd];
__device__ float g_k[Tt*KVh*HDd];
__device__ float g_v[Tt*KVh*HDd];
__device__ float g_scores[(size_t)Bz*Hh*Ss*Ss];   // 134 MB
__device__ float g_o[Tt*Hh*HDd];
__device__ float g_gbuf[(size_t)Ee*Tt*Ff];        // 67 MB per-expert gate
__device__ float g_ubuf[(size_t)Ee*Tt*Ff];        // 67 MB per-expert up
__device__ float g_dbuf[(size_t)Ee*Tt*Dd];        // 67 MB per-slot down output
__device__ int   g_eidx[Ee*Tt];
__device__ float g_egate[Ee*Tt];
__device__ int   g_ecnt[Ee];
__device__ int   g_slot[2*Tt];                    // token -> its two (e*Tt+pos) slots

// ---------------- helpers ----------------
__device__ __forceinline__ float tf32r(float x) {
    uint32_t u;
    asm("cvt.rna.tf32.f32 %0, %1;" : "=r"(u) : "f"(x));
    return __uint_as_float(u);
}

__device__ __forceinline__ void mma8(float* c, const uint32_t* a, const uint32_t* b) {
    asm volatile("mma.sync.aligned.m16n8k8.row.col.f32.tf32.tf32.f32 "
                 "{%0,%1,%2,%3}, {%4,%5,%6,%7}, {%8,%9}, {%0,%1,%2,%3};"
                 : "+f"(c[0]), "+f"(c[1]), "+f"(c[2]), "+f"(c[3])
                 : "r"(a[0]), "r"(a[1]), "r"(a[2]), "r"(a[3]),
                   "r"(b[0]), "r"(b[1]));
}

__device__ __forceinline__ float blockReduceSum256(float v) {
    __shared__ float sh[32];
    int lane = threadIdx.x & 31, wid = threadIdx.x >> 5;
    #pragma unroll
    for (int o = 16; o; o >>= 1) v += __shfl_xor_sync(0xffffffffu, v, o);
    if (lane == 0) sh[wid] = v;
    __syncthreads();
    int nw = (blockDim.x + 31) >> 5;
    float r = (threadIdx.x < nw) ? sh[threadIdx.x] : 0.f;
    if (wid == 0) {
        #pragma unroll
        for (int o = 16; o; o >>= 1) r += __shfl_xor_sync(0xffffffffu, r, o);
        if (lane == 0) sh[0] = r;
    }
    __syncthreads();
    float out = sh[0];
    __syncthreads();
    return out;
}

__device__ __forceinline__ float blockReduceMax256(float v) {
    __shared__ float sh[32];
    int lane = threadIdx.x & 31, wid = threadIdx.x >> 5;
    #pragma unroll
    for (int o = 16; o; o >>= 1) v = fmaxf(v, __shfl_xor_sync(0xffffffffu, v, o));
    if (lane == 0) sh[wid] = v;
    __syncthreads();
    int nw = (blockDim.x + 31) >> 5;
    float r = (threadIdx.x < nw) ? sh[threadIdx.x] : -INFINITY;
    if (wid == 0) {
        #pragma unroll
        for (int o = 16; o; o >>= 1) r = fmaxf(r, __shfl_xor_sync(0xffffffffu, r, o));
        if (lane == 0) sh[0] = r;
    }
    __syncthreads();
    float out = sh[0];
    __syncthreads();
    return out;
}

// ---------------- elementwise kernels ----------------
__global__ void embed_k(const int* __restrict__ tok, const float* __restrict__ emb,
                        float* __restrict__ x) {
    int i = blockIdx.x * 256 + threadIdx.x;
    int t = i / Dd, d = i % Dd;
    x[i] = emb[(long)tok[t] * Dd + d];
}

__global__ void rmsnorm_k(const float* __restrict__ x, const float* __restrict__ w,
                          float* __restrict__ out) {
    int row = blockIdx.x;
    const float* xr = x + (long)row * Dd;
    float* orow = out + (long)row * Dd;
    float ss = 0.f;
    #pragma unroll
    for (int i = 0; i < 4; i++) {
        float v = xr[threadIdx.x + i * 256];
        ss += v * v;
    }
    float tot = blockReduceSum256(ss);
    float scale = rsqrtf(tot / (float)Dd + 1e-6f);
    #pragma unroll
    for (int i = 0; i < 4; i++) {
        int d = threadIdx.x + i * 256;
        orow[d] = xr[d] * scale * w[d];
    }
}

// fused per-head RMSNorm + RoPE over Q and K, in place. 64 threads = one (token, head)
__global__ void qknorm_rope2_k(float* __restrict__ q, float* __restrict__ k,
                               const float* __restrict__ qnw, const float* __restrict__ knw,
                               const int* __restrict__ pos) {
    int bid = blockIdx.x;
    float* v;
    const float* nw;
    int t;
    if (bid < Tt * Hh) {
        t = bid / Hh;
        v = q + (long)t * (Hh * HDd) + (bid % Hh) * HDd;
        nw = qnw;
    } else {
        int b2 = bid - Tt * Hh;
        t = b2 / KVh;
        v = k + (long)t * (KVh * HDd) + (b2 % KVh) * HDd;
        nw = knw;
    }
    int d = threadIdx.x;
    float x = v[d];
    float ss = x * x;
    #pragma unroll
    for (int o = 16; o; o >>= 1) ss += __shfl_xor_sync(0xffffffffu, ss, o);
    __shared__ float s2[2];
    if ((d & 31) == 0) s2[d >> 5] = ss;
    __syncthreads();
    float tot = s2[0] + s2[1];
    float scale = rsqrtf(tot / 64.f + 1e-6f);
    float xn = x * scale * nw[d];
    __shared__ float sh[64];
    sh[d] = xn;
    __syncthreads();
    int p = pos[t];
    int fi = d & 31;
    float inv = powf(1e6f, -(float)fi / 32.f);
    float ang = (float)p * inv;
    float c = cosf(ang), s = sinf(ang);
    float other = (d < 32) ? sh[d + 32] : sh[d - 32];
    float rot = (d < 32) ? -other : other;
    v[d] = xn * c + rot * s;
}

// causal softmax; zero-fills only (q, bandEnd) — P.V's trapezoid-K never reads past it
__global__ void softmax_k(float* __restrict__ scores) {
    long row = blockIdx.x;                 // B*H*S rows
    int q = (int)(row % Ss);
    float* p = scores + row * Ss;
    int valid = q + 1;
    float mx = -INFINITY;
    for (int j = threadIdx.x; j < valid; j += 256) mx = fmaxf(mx, p[j]);
    mx = blockReduceMax256(mx);
    float sum = 0.f;
    for (int j = threadIdx.x; j < valid; j += 256) {
        float e = expf(p[j] - mx);
        p[j] = e;
        sum += e;
    }
    sum = blockReduceSum256(sum);
    float inv = 1.f / sum;
    for (int j = threadIdx.x; j < valid; j += 256) p[j] *= inv;
    int bandEnd = ((q >> 6) + 1) << 6;
    for (int j = valid + threadIdx.x; j < bandEnd; j += 256) p[j] = 0.f;
}

__global__ void zero_cnt_k(int* c) { if (threadIdx.x < Ee) c[threadIdx.x] = 0; }

// router: logits = h @ rw [D,E]; top-2; normalize; fill expert lists + token slots
__global__ void router_k(const float* __restrict__ h, const float* __restrict__ rw,
                         int* __restrict__ ecnt, int* __restrict__ eidx,
                         float* __restrict__ egate, int* __restrict__ slot) {
    int t = blockIdx.x;
    int lane = threadIdx.x & 31, w = threadIdx.x >> 5;   // warp per expert
    const float* hr = h + (long)t * Dd;
    float s = 0.f;
    for (int d = lane; d < Dd; d += 32) s += hr[d] * rw[(long)d * Ee + w];
    #pragma unroll
    for (int o = 16; o; o >>= 1) s += __shfl_xor_sync(0xffffffffu, s, o);
    __shared__ float lg[Ee];
    if (lane == 0) lg[w] = s;
    __syncthreads();
    if (threadIdx.x == 0) {
        int a = 0;
        #pragma unroll
        for (int i = 1; i < Ee; i++) if (lg[i] > lg[a]) a = i;
        int b = (a == 0) ? 1 : 0;
        #pragma unroll
        for (int i = 0; i < Ee; i++) if (i != a && lg[i] > lg[b]) b = i;
        float wa = 1.f / (1.f + expf(lg[b] - lg[a]));
        float wb = 1.f - wa;
        int pa = atomicAdd(&ecnt[a], 1);
        eidx[a * Tt + pa] = t; egate[a * Tt + pa] = wa;
        int pb = atomicAdd(&ecnt[b], 1);
        eidx[b * Tt + pb] = t; egate[b * Tt + pb] = wb;
        slot[2 * t + 0] = a * Tt + pa;
        slot[2 * t + 1] = b * Tt + pb;
    }
}

// compacted silu*up: exactly 2*Tt active rows across experts (sum(cnt) == 2*Tt)
__global__ void silu_compact_k(float* __restrict__ g, const float* __restrict__ u,
                               const int* __restrict__ cnt) {
    long i = (long)blockIdx.x * 256 + threadIdx.x;   // [0, 2*Tt*Ff)
    int r = (int)(i / Ff), col = (int)(i % Ff);
    int e = -1, lr = 0, acc = 0;
    #pragma unroll
    for (int j = 0; j < Ee; j++) {
        int c = cnt[j];
        if (e < 0 && r < acc + c) { e = j; lr = r - acc; }
        acc += c;
    }
    if (e < 0) return;
    long idx = (long)e * ((long)Tt * Ff) + (long)lr * Ff + col;
    float x = g[idx];
    g[idx] = (x / (1.f + expf(-x))) * u[idx];
}

// deterministic combine: x[t] += gate0*dbuf[slot0] + gate1*dbuf[slot1]
__global__ void combine_k(float* __restrict__ x, const float* __restrict__ dbuf,
                          const int* __restrict__ slot, const float* __restrict__ eg) {
    long i = (long)blockIdx.x * 256 + threadIdx.x;   // Tt*Dd
    int t = (int)(i / Dd), d = (int)(i % Dd);
    int s0 = slot[2 * t], s1 = slot[2 * t + 1];
    x[i] += eg[s0] * dbuf[(long)s0 * Dd + d] + eg[s1] * dbuf[(long)s1 * Dd + d];
}

// ========== MODE semantics (both GEMM kernels) ==========
// MODE 0: batched heads via z (b=z/nH, h=z%nH; strides sAb/sAh/...)
// MODE 1: dual output; z=0 -> (B,C), z=1 -> (B2,C2)
// MODE 2: expert dual + gather: z -> (e=z>>1, which=z&1); M=Mdev[e]
// MODE 3: expert single: z=e; M=Mdev[e]; A/B/C += e*stride
// MODE 4 (gemm64 only): triple output Q/K/V
// kTrap (gemm64 only): bound K-loop at m0+64 (P.V trapezoid)
// R13 design: raw fp32 smem, hi/lo tf32 split at fragment-load time.
// (R16's float2-packed smem REGRESSED: doubling smem bytes cost more than the
//  split-ALU it removed — these cores are smem-store-bound, not issue-bound.)

// ---------------- 3xTF32 GEMM, 64x64 tile (small/batched shapes) ----------------
template<int MODE, bool TRANSB>
__global__ void __launch_bounds__(128) gemm64_k(
    const float* __restrict__ A, const float* __restrict__ B,
    const float* __restrict__ B2, float* __restrict__ C, float* __restrict__ C2,
    int M, int N, int K, int lda, int ldb, int ldc,
    float alpha, int addC, int causal,
    const int* __restrict__ idxBase, const int* __restrict__ MdevBase,
    long sAb, long sAh, long sBb, long sBh, long sCb, long sCh,
    int nH, int hDiv, long eA, long eB, long eC,
    const float* __restrict__ B3, float* __restrict__ C3, int kTrap)
{
    const int* idx = nullptr;
    if (MODE == 0) {
        int z = blockIdx.z;
        int b = z / nH, h = z % nH;
        A += (long)b * sAb + (long)h * sAh;
        B += (long)b * sBb + (long)(h / hDiv) * sBh;
        C += (long)b * sCb + (long)h * sCh;
    } else if (MODE == 1) {
        if (blockIdx.z) { B = B2; C = C2; }
    } else if (MODE == 2) {
        int e = blockIdx.z >> 1, which = blockIdx.z & 1;
        M = MdevBase[e];
        idx = idxBase + e * Tt;
        B = (which ? B2 : B) + (long)e * eB;
        C = (which ? C2 : C) + (long)e * eC;
    } else if (MODE == 3) {
        int e = blockIdx.z;
        M = MdevBase[e];
        A += (long)e * eA;
        B += (long)e * eB;
        C += (long)e * eC;
    } else if (MODE == 4) {
        int z = blockIdx.z;
        if (z == 1) { B = B2; C = C2; N = KVh * HDd; ldb = KVh * HDd; ldc = KVh * HDd; }
        else if (z == 2) { B = B3; C = C3; N = KVh * HDd; ldb = KVh * HDd; ldc = KVh * HDd; }
    }
    constexpr bool GATHER = (MODE == 2);

    int m0 = blockIdx.y * 64, n0 = blockIdx.x * 64;
    if (m0 >= M || n0 >= N) return;
    if (causal && n0 >= m0 + 64) return;

    __shared__ float As[2][64][20];   // raw fp32; stride 20 conflict-free
    __shared__ float Bs[2][16][72];   // raw fp32; stride 72 conflict-free

    int tid = threadIdx.x;
    int lane = tid & 31, warp = tid >> 5;
    int wm = (warp >> 1) * 32, wn = (warp & 1) * 32;
    int qrow = lane >> 2, qk = lane & 3;

    int ar_r = tid >> 2;               // 0..31
    int ac4 = (tid & 3) * 4;
    int gr0 = m0 + ar_r, gr1 = gr0 + 32;
    bool av0 = gr0 < M, av1 = gr1 < M;
    long arow0 = 0, arow1 = 0;
    if (av0) arow0 = (long)(GATHER ? idx[gr0] : gr0) * lda;
    if (av1) arow1 = (long)(GATHER ? idx[gr1] : gr1) * lda;

    int bnr, bc4;
    if (TRANSB) { bnr = tid >> 2; bc4 = (tid & 3) * 4; }
    else        { bnr = tid >> 4; bc4 = (tid & 15) * 4; }

    float4 pa0, pa1, pb0, pb1;
    const float4 z4 = make_float4(0.f, 0.f, 0.f, 0.f);

    float acc[2][4][4];
    #pragma unroll
    for (int mt = 0; mt < 2; mt++)
        #pragma unroll
        for (int nt = 0; nt < 4; nt++)
            #pragma unroll
            for (int i = 0; i < 4; i++) acc[mt][nt][i] = 0.f;

    auto LDG = [&](int k0) {
        pa0 = av0 ? *(const float4*)(A + arow0 + k0 + ac4) : z4;
        pa1 = av1 ? *(const float4*)(A + arow1 + k0 + ac4) : z4;
        if (TRANSB) {
            pb0 = *(const float4*)(B + (long)(n0 + bnr) * ldb + k0 + bc4);
            pb1 = *(const float4*)(B + (long)(n0 + bnr + 32) * ldb + k0 + bc4);
        } else {
            pb0 = *(const float4*)(B + (long)(k0 + bnr) * ldb + n0 + bc4);
            pb1 = *(const float4*)(B + (long)(k0 + bnr + 8) * ldb + n0 + bc4);
        }
    };

    auto STS = [&](int buf) {
        *(float4*)&As[buf][ar_r][ac4] = pa0;
        *(float4*)&As[buf][ar_r + 32][ac4] = pa1;
        if (TRANSB) {
            Bs[buf][bc4 + 0][bnr] = pb0.x;
            Bs[buf][bc4 + 1][bnr] = pb0.y;
            Bs[buf][bc4 + 2][bnr] = pb0.z;
            Bs[buf][bc4 + 3][bnr] = pb0.w;
            Bs[buf][bc4 + 0][bnr + 32] = pb1.x;
            Bs[buf][bc4 + 1][bnr + 32] = pb1.y;
            Bs[buf][bc4 + 2][bnr + 32] = pb1.z;
            Bs[buf][bc4 + 3][bnr + 32] = pb1.w;
        } else {
            *(float4*)&Bs[buf][bnr][bc4] = pb0;
            *(float4*)&Bs[buf][bnr + 8][bc4] = pb1;
        }
    };

    auto split = [&](float v, uint32_t& hi, uint32_t& lo) {
        float h = tf32r(v);
        hi = __float_as_uint(h);
        lo = __float_as_uint(tf32r(v - h));
    };

    auto COMPUTE = [&](int buf) {
        #pragma unroll
        for (int ks = 0; ks < 2; ks++) {
            int kk = ks * 8 + qk;
            uint32_t afh[2][4], afl[2][4];
            #pragma unroll
            for (int mt = 0; mt < 2; mt++) {
                int r = wm + mt * 16 + qrow;
                split(As[buf][r][kk],          afh[mt][0], afl[mt][0]);
                split(As[buf][r + 8][kk],      afh[mt][1], afl[mt][1]);
                split(As[buf][r][kk + 4],      afh[mt][2], afl[mt][2]);
                split(As[buf][r + 8][kk + 4],  afh[mt][3], afl[mt][3]);
            }
            uint32_t bfh[4][2], bfl[4][2];
            #pragma unroll
            for (int nt = 0; nt < 4; nt++) {
                int cn = wn + nt * 8 + qrow;
                split(Bs[buf][kk][cn],      bfh[nt][0], bfl[nt][0]);
                split(Bs[buf][kk + 4][cn],  bfh[nt][1], bfl[nt][1]);
            }
            #pragma unroll
            for (int mt = 0; mt < 2; mt++)
                #pragma unroll
                for (int nt = 0; nt < 4; nt++) {
                    mma8(acc[mt][nt], afh[mt], bfl[nt]);
                    mma8(acc[mt][nt], afl[mt], bfh[nt]);
                    mma8(acc[mt][nt], afh[mt], bfh[nt]);
                }
        }
    };

    int KT = K >> 4;
    if (kTrap) {
        int kt2 = (m0 + 64) >> 4;
        if (kt2 < KT) KT = kt2;
    }
    LDG(0);
    STS(0);
    __syncthreads();
    for (int kt = 0; kt < KT; kt++) {
        int cur = kt & 1;
        bool more = (kt + 1) < KT;
        if (more) LDG((kt + 1) * 16);
        COMPUTE(cur);
        if (more) {
            __syncthreads();
            STS(cur ^ 1);
            __syncthreads();
        }
    }

    #pragma unroll
    for (int mt = 0; mt < 2; mt++) {
        #pragma unroll
        for (int half = 0; half < 2; half++) {
            int m = m0 + wm + mt * 16 + qrow + half * 8;
            if (m >= M) continue;
            long crow = (long)m * ldc;
            #pragma unroll
            for (int nt = 0; nt < 4; nt++) {
                int col = n0 + wn + nt * 8 + 2 * qk;
                float v0 = alpha * acc[mt][nt][half * 2 + 0];
                float v1 = alpha * acc[mt][nt][half * 2 + 1];
                float2* cp = (float2*)(C + crow + col);
                if (addC) {
                    float2 old = *cp;
                    old.x += v0; old.y += v1;
                    *cp = old;
                } else {
                    *cp = make_float2(v0, v1);
                }
            }
        }
    }
}

// ---------------- 3xTF32 GEMM, 128x128 tile (large shapes) ----------------
template<int MODE, bool TRANSB>
__global__ void __launch_bounds__(256, 2) gemm128_k(
    const float* __restrict__ A, const float* __restrict__ B,
    const float* __restrict__ B2, float* __restrict__ C, float* __restrict__ C2,
    int M, int N, int K, int lda, int ldb, int ldc,
    float alpha, int addC, int causal,
    const int* __restrict__ idxBase, const int* __restrict__ MdevBase,
    long sAb, long sAh, long sBb, long sBh, long sCb, long sCh,
    int nH, int hDiv, long eA, long eB, long eC)
{
    const int* idx = nullptr;
    if (MODE == 0) {
        int z = blockIdx.z;
        int b = z / nH, h = z % nH;
        A += (long)b * sAb + (long)h * sAh;
        B += (long)b * sBb + (long)(h / hDiv) * sBh;
        C += (long)b * sCb + (long)h * sCh;
    } else if (MODE == 1) {
        if (blockIdx.z) { B = B2; C = C2; }
    } else if (MODE == 2) {
        int e = blockIdx.z >> 1, which = blockIdx.z & 1;
        M = MdevBase[e];
        idx = idxBase + e * Tt;
        B = (which ? B2 : B) + (long)e * eB;
        C = (which ? C2 : C) + (long)e * eC;
    } else if (MODE == 3) {
        int e = blockIdx.z;
        M = MdevBase[e];
        A += (long)e * eA;
        B += (long)e * eB;
        C += (long)e * eC;
    }
    constexpr bool GATHER = (MODE == 2);

    int m0 = blockIdx.y * 128, n0 = blockIdx.x * 128;
    if (m0 >= M) return;
    if (causal && n0 >= m0 + 128) return;

    __shared__ float As[2][128][20];   // stride 20: conflict-free frag reads
    __shared__ float Bs[2][16][136];   // stride 136 (=8 mod 32): conflict-free

    int tid = threadIdx.x;
    int lane = tid & 31, warp = tid >> 5;
    int wm = (warp >> 2) * 64, wn = (warp & 3) * 32;
    int qrow = lane >> 2, qk = lane & 3;

    int ar_r = tid >> 2;               // 0..63
    int ac4 = (tid & 3) * 4;
    int gr0 = m0 + ar_r, gr1 = gr0 + 64;
    bool av0 = gr0 < M, av1 = gr1 < M;
    long arow0 = 0, arow1 = 0;
    if (av0) arow0 = (long)(GATHER ? idx[gr0] : gr0) * lda;
    if (av1) arow1 = (long)(GATHER ? idx[gr1] : gr1) * lda;

    int bnr, bc4;
    bool bv0, bv1;
    if (TRANSB) {
        bnr = tid >> 2; bc4 = (tid & 3) * 4;       // n-rows bnr, bnr+64
        bv0 = (n0 + bnr) < N; bv1 = (n0 + bnr + 64) < N;
    } else {
        bnr = tid >> 5; bc4 = (tid & 31) * 4;      // k-rows bnr, bnr+8
        bv0 = bv1 = (n0 + bc4) < N;
    }

    float4 pa0, pa1, pb0, pb1;
    const float4 z4 = make_float4(0.f, 0.f, 0.f, 0.f);

    float acc[4][4][4];
    #pragma unroll
    for (int mt = 0; mt < 4; mt++)
        #pragma unroll
        for (int nt = 0; nt < 4; nt++)
            #pragma unroll
            for (int i = 0; i < 4; i++) acc[mt][nt][i] = 0.f;

    auto LDG = [&](int k0) {
        pa0 = av0 ? *(const float4*)(A + arow0 + k0 + ac4) : z4;
        pa1 = av1 ? *(const float4*)(A + arow1 + k0 + ac4) : z4;
        if (TRANSB) {
            pb0 = bv0 ? *(const float4*)(B + (long)(n0 + bnr) * ldb + k0 + bc4) : z4;
            pb1 = bv1 ? *(const float4*)(B + (long)(n0 + bnr + 64) * ldb + k0 + bc4) : z4;
        } else {
            pb0 = bv0 ? *(const float4*)(B + (long)(k0 + bnr) * ldb + n0 + bc4) : z4;
            pb1 = bv1 ? *(const float4*)(B + (long)(k0 + bnr + 8) * ldb + n0 + bc4) : z4;
        }
    };

    auto STS = [&](int buf) {
        *(float4*)&As[buf][ar_r][ac4] = pa0;
        *(float4*)&As[buf][ar_r + 64][ac4] = pa1;
        if (TRANSB) {
            Bs[buf][bc4 + 0][bnr] = pb0.x;
            Bs[buf][bc4 + 1][bnr] = pb0.y;
            Bs[buf][bc4 + 2][bnr] = pb0.z;
            Bs[buf][bc4 + 3][bnr] = pb0.w;
            Bs[buf][bc4 + 0][bnr + 64] = pb1.x;
            Bs[buf][bc4 + 1][bnr + 64] = pb1.y;
            Bs[buf][bc4 + 2][bnr + 64] = pb1.z;
            Bs[buf][bc4 + 3][bnr + 64] = pb1.w;
        } else {
            *(float4*)&Bs[buf][bnr][bc4] = pb0;
            *(float4*)&Bs[buf][bnr + 8][bc4] = pb1;
        }
    };

    auto split = [&](float v, uint32_t& hi, uint32_t& lo) {
        float h = tf32r(v);
        hi = __float_as_uint(h);
        lo = __float_as_uint(tf32r(v - h));
    };

    auto COMPUTE = [&](int buf) {
        #pragma unroll
        for (int ks = 0; ks < 2; ks++) {
            int kk = ks * 8 + qk;
            uint32_t afh[4][4], afl[4][4];
            #pragma unroll
            for (int mt = 0; mt < 4; mt++) {
                int r = wm + mt * 16 + qrow;
                split(As[buf][r][kk],          afh[mt][0], afl[mt][0]);
                split(As[buf][r + 8][kk],      afh[mt][1], afl[mt][1]);
                split(As[buf][r][kk + 4],      afh[mt][2], afl[mt][2]);
                split(As[buf][r + 8][kk + 4],  afh[mt][3], afl[mt][3]);
            }
            uint32_t bfh[4][2], bfl[4][2];
            #pragma unroll
            for (int nt = 0; nt < 4; nt++) {
                int cn = wn + nt * 8 + qrow;
                split(Bs[buf][kk][cn],      bfh[nt][0], bfl[nt][0]);
                split(Bs[buf][kk + 4][cn],  bfh[nt][1], bfl[nt][1]);
            }
            #pragma unroll
            for (int mt = 0; mt < 4; mt++)
                #pragma unroll
                for (int nt = 0; nt < 4; nt++) {
                    mma8(acc[mt][nt], afh[mt], bfl[nt]);
                    mma8(acc[mt][nt], afl[mt], bfh[nt]);
                    mma8(acc[mt][nt], afh[mt], bfh[nt]);
                }
        }
    };

    int KT = K >> 4;
    LDG(0);
    STS(0);
    __syncthreads();
    for (int kt = 0; kt < KT; kt++) {
        int cur = kt & 1;
        bool more = (kt + 1) < KT;
        if (more) LDG((kt + 1) * 16);
        COMPUTE(cur);
        if (more) {
            __syncthreads();
            STS(cur ^ 1);
            __syncthreads();
        }
    }

    #pragma unroll
    for (int mt = 0; mt < 4; mt++) {
        #pragma unroll
        for (int half = 0; half < 2; half++) {
            int m = m0 + wm + mt * 16 + qrow + half * 8;
            if (m >= M) continue;
            long crow = (long)m * ldc;
            #pragma unroll
            for (int nt = 0; nt < 4; nt++) {
                int colg = n0 + wn + nt * 8;
                if (colg >= N) continue;
                int col = colg + 2 * qk;
                float v0 = alpha * acc[mt][nt][half * 2 + 0];
                float v1 = alpha * acc[mt][nt][half * 2 + 1];
                float2* cp = (float2*)(C + crow + col);
                if (addC) {
                    float2 old = *cp;
                    old.x += v0; old.y += v1;
                    *cp = old;
                } else {
                    *cp = make_float2(v0, v1);
                }
            }
        }
    }
}

// ---------------- host side ----------------
extern "C" void kernel_launch(void* const* d_in, const int* in_sizes, int n_in,
                              void* d_out, int out_size) {
    const int*   tok    = (const int*)d_in[0];
    const int*   pos    = (const int*)d_in[1];
    const float* emb    = (const float*)d_in[2];
    const float* attnw  = (const float*)d_in[3];
    const float* wq     = (const float*)d_in[4];
    const float* wk     = (const float*)d_in[5];
    const float* wv     = (const float*)d_in[6];
    const float* qnw    = (const float*)d_in[7];
    const float* knw    = (const float*)d_in[8];
    const float* wo     = (const float*)d_in[9];
    const float* ffnw   = (const float*)d_in[10];
    const float* rw     = (const float*)d_in[11];
    const float* gw     = (const float*)d_in[12];
    const float* uw     = (const float*)d_in[13];
    const float* dw     = (const float*)d_in[14];
    const float* fnw    = (const float*)d_in[15];
    float* out = (float*)d_out;

    float *px, *ph, *pq, *pk, *pv, *po, *pscores, *pgbuf, *pubuf, *pdbuf, *pegate;
    int *peidx, *pecnt, *pslot;
    cudaGetSymbolAddress((void**)&px, g_x);
    cudaGetSymbolAddress((void**)&ph, g_h);
    cudaGetSymbolAddress((void**)&pq, g_q);
    cudaGetSymbolAddress((void**)&pk, g_k);
    cudaGetSymbolAddress((void**)&pv, g_v);
    cudaGetSymbolAddress((void**)&po, g_o);
    cudaGetSymbolAddress((void**)&pscores, g_scores);
    cudaGetSymbolAddress((void**)&pgbuf, g_gbuf);
    cudaGetSymbolAddress((void**)&pubuf, g_ubuf);
    cudaGetSymbolAddress((void**)&pdbuf, g_dbuf);
    cudaGetSymbolAddress((void**)&pegate, g_egate);
    cudaGetSymbolAddress((void**)&peidx, g_eidx);
    cudaGetSymbolAddress((void**)&pecnt, g_ecnt);
    cudaGetSymbolAddress((void**)&pslot, g_slot);

    const long ZL = 0;

    // embed
    embed_k<<<(Tt * Dd) / 256, 256>>>(tok, emb, px);

    for (int l = 0; l < Ll; l++) {
        const float* wq_l = wq + (long)l * Dd * (Hh * HDd);
        const float* wk_l = wk + (long)l * Dd * (KVh * HDd);
        const float* wv_l = wv + (long)l * Dd * (KVh * HDd);
        const float* wo_l = wo + (long)l * (Hh * HDd) * Dd;
        const float* gw_l = gw + (long)l * Ee * Dd * Ff;
        const float* uw_l = uw + (long)l * Ee * Dd * Ff;
        const float* dw_l = dw + (long)l * Ee * Ff * Dd;

        // ---- attention ----
        rmsnorm_k<<<Tt, 256>>>(px, attnw + (long)l * Dd, ph);

        // Q + K + V fused in ONE launch (MODE 4: z=0 Q, z=1 K, z=2 V)
        gemm64_k<4,false><<<dim3(16, 32, 3), 128>>>(
            ph, wq_l, wk_l, pq, pk,
            Tt, Hh * HDd, Dd, Dd, Hh * HDd, Hh * HDd,
            1.f, 0, 0, nullptr, nullptr,
            ZL, ZL, ZL, ZL, ZL, ZL, 1, 1, ZL, ZL, ZL,
            wv_l, pv, 0);

        // fused q+k norm/rope
        qknorm_rope2_k<<<Tt * (Hh + KVh), 64>>>(pq, pk, qnw + (long)l * HDd,
                                                knw + (long)l * HDd, pos);

        // scores = Q @ K^T * scale (128-tile, batched, causal skip)
        gemm128_k<0,true><<<dim3(8, 8, Bz * Hh), 256>>>(
            pq, pk, nullptr, pscores, nullptr,
            Ss, Ss, HDd, Hh * HDd, KVh * HDd, Ss,
            0.125f, 0, 1, nullptr, nullptr,
            (long)Ss * Hh * HDd, (long)HDd,
            (long)Ss * KVh * HDd, (long)HDd,
            (long)Hh * Ss * Ss, (long)Ss * Ss,
            Hh, Hh / KVh, ZL, ZL, ZL);

        softmax_k<<<Bz * Hh * Ss, 256>>>(pscores);

        // O = P @ V (64-tile, trapezoid-K: K loop bounded at m0+64)
        gemm64_k<0,false><<<dim3(1, 16, Bz * Hh), 128>>>(
            pscores, pv, nullptr, po, nullptr,
            Ss, HDd, Ss, Ss, KVh * HDd, Hh * HDd,
            1.f, 0, 0, nullptr, nullptr,
            (long)Hh * Ss * Ss, (long)Ss * Ss,
            (long)Ss * KVh * HDd, (long)HDd,
            (long)Ss * Hh * HDd, (long)HDd,
            Hh, Hh / KVh, ZL, ZL, ZL,
            nullptr, nullptr, 1);

        // x += O @ wo (64-tile: grid 512)
        gemm64_k<0,false><<<dim3(16, 32, 1), 128>>>(
            po, wo_l, nullptr, px, nullptr,
            Tt, Dd, Hh * HDd, Hh * HDd, Dd, Dd,
            1.f, 1, 0, nullptr, nullptr,
            ZL, ZL, ZL, ZL, ZL, ZL, 1, 1, ZL, ZL, ZL,
            nullptr, nullptr, 0);

        // ---- MoE ----
        rmsnorm_k<<<Tt, 256>>>(px, ffnw + (long)l * Dd, ph);
        zero_cnt_k<<<1, 32>>>(pecnt);
        router_k<<<Tt, 256>>>(ph, rw + (long)l * Dd * Ee, pecnt, peidx, pegate, pslot);

        // all experts' gate+up in ONE launch (128-tile): z = e*2 + which
        gemm128_k<2,false><<<dim3(8, 16, 2 * Ee), 256>>>(
            ph, gw_l, uw_l, pgbuf, pubuf,
            Tt, Ff, Dd, Dd, Ff, Ff,
            1.f, 0, 0, peidx, pecnt,
            ZL, ZL, ZL, ZL, ZL, ZL, 1, 1,
            ZL, (long)Dd * Ff, (long)Tt * Ff);

        // compacted silu*up over exactly the 2*Tt active rows
        silu_compact_k<<<(int)(((long)2 * Tt * Ff) / 256), 256>>>(pgbuf, pubuf, pecnt);

        // all experts' down-proj in ONE launch (128-tile) -> per-slot buffer
        gemm128_k<3,false><<<dim3(8, 16, Ee), 256>>>(
            pgbuf, dw_l, nullptr, pdbuf, nullptr,
            Tt, Dd, Ff, Ff, Dd, Dd,
            1.f, 0, 0, nullptr, pecnt,
            ZL, ZL, ZL, ZL, ZL, ZL, 1, 1,
            (long)Tt * Ff, (long)Ff * Dd, (long)Tt * Dd);

        // deterministic combine: x += gate0*y0 + gate1*y1
        combine_k<<<(Tt * Dd) / 256, 256>>>(px, pdbuf, pslot, pegate);
    }

    // final norm + tied lm_head (128-tile: grid 250x16 = 4000)
    rmsnorm_k<<<Tt, 256>>>(px, fnw, ph);
    gemm128_k<0,true><<<dim3(Vv / 128, Tt / 128, 1), 256>>>(
        ph, emb, nullptr, out, nullptr,
        Tt, Vv, Dd, Dd, Dd, Vv,
        1.f, 0, 0, nullptr, nullptr,
        ZL, ZL, ZL, ZL, ZL, ZL, 1, 1, ZL, ZL, ZL);
}